// round 1
// baseline (speedup 1.0000x reference)
#include <cuda_runtime.h>
#include <math.h>

#define NN 231          // nodes per graph
#define BT 16           // graphs per block
#define THREADS 256
#define MAXM 4096       // cap on edges incl. self loops (actual ~2079)

// ---------------- persistent CSR built by prep kernel ----------------
__device__ int   g_row_ptr[NN + 1];
__device__ int   g_csr_src[MAXM];
__device__ float g_csr_w[MAXM];

// =====================================================================
// Prep kernel: build deterministic CSR (stable counting sort by dst)
// and symmetric-norm edge weights. One block, runs in a few us.
// =====================================================================
__global__ void prep_kernel(const void* __restrict__ ei, int E) {
    __shared__ short s_src[2304];
    __shared__ short s_dst[2304];
    __shared__ int   deg[NN];
    __shared__ int   rp[NN + 1];
    __shared__ float inv[NN];
    __shared__ int   cnt[32][NN];
    __shared__ int   is64;

    const int tid = threadIdx.x;
    const int M = E + NN;

    if (tid == 0) {
        // detect int64 vs int32 edge_index (jax may silently emit int32)
        const long long* p = (const long long*)ei;
        int ok = 1;
        for (int i = 0; i < 8; i++) {
            long long v = p[i];
            if (v < 0 || v >= NN) ok = 0;
        }
        is64 = ok;
    }
    for (int n = tid; n < NN; n += blockDim.x) deg[n] = 0;
    __syncthreads();

    for (int e = tid; e < M; e += blockDim.x) {
        int s, d;
        if (e < E) {
            if (is64) {
                s = (int)((const long long*)ei)[e];
                d = (int)((const long long*)ei)[E + e];
            } else {
                s = ((const int*)ei)[e];
                d = ((const int*)ei)[E + e];
            }
        } else {           // self loops appended after real edges
            s = d = e - E;
        }
        s_src[e] = (short)s;
        s_dst[e] = (short)d;
        atomicAdd(&deg[d], 1);   // integer: deterministic
    }
    __syncthreads();

    for (int n = tid; n < NN; n += blockDim.x)
        inv[n] = rsqrtf((float)max(deg[n], 1));
    if (tid == 0) {
        int acc = 0;
        for (int n = 0; n < NN; n++) { rp[n] = acc; acc += deg[n]; }
        rp[NN] = acc;
    }
    for (int i = tid; i < 32 * NN; i += blockDim.x)
        ((int*)cnt)[i] = 0;
    __syncthreads();

    const int chunk = (M + 31) / 32;
    if (tid < 32) {
        int e0 = tid * chunk, e1 = min(e0 + chunk, M);
        for (int e = e0; e < e1; e++) cnt[tid][s_dst[e]]++;
    }
    __syncthreads();

    // exclusive offsets per (bucket, thread) -> stable & deterministic
    for (int n = tid; n < NN; n += blockDim.x) {
        int run = rp[n];
        for (int t = 0; t < 32; t++) {
            int c = cnt[t][n];
            cnt[t][n] = run;
            run += c;
        }
    }
    __syncthreads();

    if (tid < 32) {
        int e0 = tid * chunk, e1 = min(e0 + chunk, M);
        for (int e = e0; e < e1; e++) {
            int d = s_dst[e], s = s_src[e];
            int pos = cnt[tid][d]++;
            g_csr_src[pos] = s;
            g_csr_w[pos]   = inv[s] * inv[d];
        }
    }
    __syncthreads();
    for (int n = tid; n <= NN; n += blockDim.x) g_row_ptr[n] = rp[n];
}

// =====================================================================
// Fused kernel: per block, BT=16 graphs, full GCN + MLP in shared mem.
// Shared layout [node][feat][b] (b innermost, coalesced, atomic-free).
// =====================================================================

__device__ __forceinline__ float elu1(float v) {
    return v > 0.0f ? v : expm1f(v);
}

// small-weight shared offsets (floats)
#define O_W1  0      // 12x8
#define O_B1  96     // 8
#define O_W2  104    // 8x4
#define O_B2  136    // 4
#define O_W3  140    // 4x2
#define O_B3  148    // 2
#define O_BF1 152    // 120
#define O_BF2 272    // 84
#define O_BF3 356    // 10
#define O_SMALL_END 368

__global__ void __launch_bounds__(THREADS)
gcn_fused_kernel(const float* __restrict__ x,
                 const float* __restrict__ W1, const float* __restrict__ b1,
                 const float* __restrict__ W2, const float* __restrict__ b2,
                 const float* __restrict__ W3, const float* __restrict__ b3,
                 const float* __restrict__ Wf1, const float* __restrict__ bf1,
                 const float* __restrict__ Wf2, const float* __restrict__ bf2,
                 const float* __restrict__ Wf3, const float* __restrict__ bf3,
                 float* __restrict__ out, int B, int M) {
    extern __shared__ float sm[];
    float* S1      = sm;                    // 231*8*16 = 29568 floats
    float* S2      = S1 + NN * 8 * BT;      // 231*4*16 = 14784 floats
    float* s_w     = S2 + NN * 4 * BT;      // M edge weights
    float* s_small = s_w + M;               // small weights+biases (512)
    int*   s_rp    = (int*)(s_small + 512); // 232
    int*   s_src   = s_rp + (NN + 1);       // M

    const int tid = threadIdx.x;
    const int b0  = blockIdx.x * BT;

    // ---- stage CSR + small weights into shared ----
    for (int i = tid; i <= NN; i += THREADS) s_rp[i] = g_row_ptr[i];
    for (int i = tid; i < M; i += THREADS) {
        s_src[i] = g_csr_src[i];
        s_w[i]   = g_csr_w[i];
    }
    for (int i = tid; i < 96;  i += THREADS) s_small[O_W1 + i] = W1[i];
    for (int i = tid; i < 8;   i += THREADS) s_small[O_B1 + i] = b1[i];
    for (int i = tid; i < 32;  i += THREADS) s_small[O_W2 + i] = W2[i];
    for (int i = tid; i < 4;   i += THREADS) s_small[O_B2 + i] = b2[i];
    for (int i = tid; i < 8;   i += THREADS) s_small[O_W3 + i] = W3[i];
    for (int i = tid; i < 2;   i += THREADS) s_small[O_B3 + i] = b3[i];
    for (int i = tid; i < 120; i += THREADS) s_small[O_BF1 + i] = bf1[i];
    for (int i = tid; i < 84;  i += THREADS) s_small[O_BF2 + i] = bf2[i];
    for (int i = tid; i < 10;  i += THREADS) s_small[O_BF3 + i] = bf3[i];
    __syncthreads();

    // ================= Phase T1: t1 = x @ W1  -> S1[n][8][b] ==========
    for (int idx = tid; idx < NN * BT; idx += THREADS) {
        const int n = idx >> 4, b = idx & 15;
        const int g = b0 + b;
        float xa[12];
        if (g < B) {
            const float4* xp = (const float4*)(x + ((size_t)g * NN + n) * 12);
            float4 v0 = xp[0], v1 = xp[1], v2 = xp[2];
            xa[0] = v0.x; xa[1] = v0.y; xa[2]  = v0.z; xa[3]  = v0.w;
            xa[4] = v1.x; xa[5] = v1.y; xa[6]  = v1.z; xa[7]  = v1.w;
            xa[8] = v2.x; xa[9] = v2.y; xa[10] = v2.z; xa[11] = v2.w;
        } else {
            #pragma unroll
            for (int c = 0; c < 12; c++) xa[c] = 0.0f;
        }
        #pragma unroll
        for (int f = 0; f < 8; f++) {
            float a = 0.0f;
            #pragma unroll
            for (int c = 0; c < 12; c++) a += xa[c] * s_small[O_W1 + c * 8 + f];
            S1[(n * 8 + f) * BT + b] = a;
        }
    }
    __syncthreads();

    // ===== Phase A1: agg(t1)+b1 -> tanh -> @W2 -> S2[n][4][b] =========
    for (int idx = tid; idx < NN * BT; idx += THREADS) {
        const int n = idx >> 4, b = idx & 15;
        float acc[8];
        #pragma unroll
        for (int f = 0; f < 8; f++) acc[f] = s_small[O_B1 + f];
        const int j1 = s_rp[n + 1];
        for (int j = s_rp[n]; j < j1; j++) {
            const int s = s_src[j];
            const float w = s_w[j];
            const float* p = &S1[s * 8 * BT + b];
            #pragma unroll
            for (int f = 0; f < 8; f++) acc[f] += w * p[f * BT];
        }
        float gg[8];
        #pragma unroll
        for (int f = 0; f < 8; f++) gg[f] = tanhf(acc[f]);
        #pragma unroll
        for (int f2 = 0; f2 < 4; f2++) {
            float a = 0.0f;
            #pragma unroll
            for (int f = 0; f < 8; f++) a += gg[f] * s_small[O_W2 + f * 4 + f2];
            S2[(n * 4 + f2) * BT + b] = a;
        }
    }
    __syncthreads();

    // ===== Phase A2: agg(t2)+b2 -> tanh -> @W3 -> S1[n][2][b] =========
    for (int idx = tid; idx < NN * BT; idx += THREADS) {
        const int n = idx >> 4, b = idx & 15;
        float acc[4];
        #pragma unroll
        for (int f = 0; f < 4; f++) acc[f] = s_small[O_B2 + f];
        const int j1 = s_rp[n + 1];
        for (int j = s_rp[n]; j < j1; j++) {
            const int s = s_src[j];
            const float w = s_w[j];
            const float* p = &S2[s * 4 * BT + b];
            #pragma unroll
            for (int f = 0; f < 4; f++) acc[f] += w * p[f * BT];
        }
        float gg[4];
        #pragma unroll
        for (int f = 0; f < 4; f++) gg[f] = tanhf(acc[f]);
        #pragma unroll
        for (int c = 0; c < 2; c++) {
            float a = 0.0f;
            #pragma unroll
            for (int f = 0; f < 4; f++) a += gg[f] * s_small[O_W3 + f * 2 + c];
            S1[(n * 2 + c) * BT + b] = a;
        }
    }
    __syncthreads();

    // ===== Phase A3: h3 = agg(t3)+b3 -> S2[k=(2n+c)][b]  (FC input) ===
    for (int idx = tid; idx < NN * BT; idx += THREADS) {
        const int n = idx >> 4, b = idx & 15;
        float acc0 = s_small[O_B3 + 0];
        float acc1 = s_small[O_B3 + 1];
        const int j1 = s_rp[n + 1];
        for (int j = s_rp[n]; j < j1; j++) {
            const int s = s_src[j];
            const float w = s_w[j];
            acc0 += w * S1[(s * 2 + 0) * BT + b];
            acc1 += w * S1[(s * 2 + 1) * BT + b];
        }
        S2[(n * 2 + 0) * BT + b] = acc0;
        S2[(n * 2 + 1) * BT + b] = acc1;
    }
    __syncthreads();

    // ===== FC1: [16,462] @ Wf1[462,120] + bf1 -> elu -> S1[j][b] ======
    {
        const int b = tid & 15, jg = tid >> 4;   // 16 jg groups, 15 used
        if (jg < 15) {
            const int j0 = jg * 8;
            float acc[8];
            #pragma unroll
            for (int i = 0; i < 8; i++) acc[i] = s_small[O_BF1 + j0 + i];
            #pragma unroll 2
            for (int k = 0; k < 462; k++) {
                const float v = S2[k * BT + b];
                const float4 w0 = __ldg((const float4*)(Wf1 + k * 120 + j0));
                const float4 w1 = __ldg((const float4*)(Wf1 + k * 120 + j0 + 4));
                acc[0] += v * w0.x; acc[1] += v * w0.y;
                acc[2] += v * w0.z; acc[3] += v * w0.w;
                acc[4] += v * w1.x; acc[5] += v * w1.y;
                acc[6] += v * w1.z; acc[7] += v * w1.w;
            }
            #pragma unroll
            for (int i = 0; i < 8; i++)
                S1[(j0 + i) * BT + b] = elu1(acc[i]);
        }
    }
    __syncthreads();

    // ===== FC2: [16,120] @ Wf2[120,84] + bf2 -> elu -> S2[j][b] =======
    {
        const int b = tid & 15, jg = tid >> 4;   // 14 groups * 6 = 84
        if (jg < 14) {
            const int j0 = jg * 6;
            float acc[6];
            #pragma unroll
            for (int i = 0; i < 6; i++) acc[i] = s_small[O_BF2 + j0 + i];
            #pragma unroll 2
            for (int k = 0; k < 120; k++) {
                const float v = S1[k * BT + b];
                #pragma unroll
                for (int i = 0; i < 6; i++)
                    acc[i] += v * __ldg(Wf2 + k * 84 + j0 + i);
            }
            #pragma unroll
            for (int i = 0; i < 6; i++)
                S2[(j0 + i) * BT + b] = elu1(acc[i]);
        }
    }
    __syncthreads();

    // ===== FC3: [16,84] @ Wf3[84,10] + bf3 -> out =====================
    if (tid < 160) {
        const int b = tid & 15, j = tid >> 4;    // j = 0..9
        float acc = s_small[O_BF3 + j];
        #pragma unroll 4
        for (int k = 0; k < 84; k++)
            acc += S2[k * BT + b] * __ldg(Wf3 + k * 10 + j);
        const int g = b0 + b;
        if (g < B) out[(size_t)g * 10 + j] = acc;
    }
}

// =====================================================================
extern "C" void kernel_launch(void* const* d_in, const int* in_sizes, int n_in,
                              void* d_out, int out_size) {
    const float* x   = (const float*)d_in[0];
    const void*  ei  = d_in[1];                     // int64 or int32 (auto-detect)
    const float* W1  = (const float*)d_in[2];
    const float* b1  = (const float*)d_in[3];
    const float* W2  = (const float*)d_in[4];
    const float* b2  = (const float*)d_in[5];
    const float* W3  = (const float*)d_in[6];
    const float* b3  = (const float*)d_in[7];
    const float* Wf1 = (const float*)d_in[8];
    const float* bf1 = (const float*)d_in[9];
    const float* Wf2 = (const float*)d_in[10];
    const float* bf2 = (const float*)d_in[11];
    const float* Wf3 = (const float*)d_in[12];
    const float* bf3 = (const float*)d_in[13];
    float* out = (float*)d_out;

    const int B = in_sizes[0] / (NN * 12);
    const int E = in_sizes[1] / 2;
    const int M = E + NN;

    prep_kernel<<<1, 256>>>(ei, E);

    const size_t smem =
        (size_t)(NN * 8 * BT + NN * 4 * BT + M + 512) * sizeof(float) +
        (size_t)(NN + 1 + M) * sizeof(int);
    static int smem_set = 0;
    if (!smem_set) {
        cudaFuncSetAttribute(gcn_fused_kernel,
                             cudaFuncAttributeMaxDynamicSharedMemorySize,
                             (int)232000);
        smem_set = 1;
    }

    const int blocks = (B + BT - 1) / BT;
    gcn_fused_kernel<<<blocks, THREADS, smem>>>(
        x, W1, b1, W2, b2, W3, b3, Wf1, bf1, Wf2, bf2, Wf3, bf3,
        out, B, M);
}

// round 2
// speedup vs baseline: 1.4945x; 1.4945x over previous
#include <cuda_runtime.h>
#include <math.h>

#define NN 231          // nodes per graph
#define BT 16           // graphs per block
#define THREADS 512
#define MAXM 4096       // cap for persistent CSR arrays
#define CAP  2112       // shared-mem cap on edges incl self loops (actual 2079)

#define S1_STRIDE 132   // 8*BT + 4 pad  (528B, != 0 mod 128 -> bank rotate)
#define S2_STRIDE 68    // 4*BT + 4 pad  (272B)
#define T3_STRIDE 36    // 2*BT + 4 pad  (144B)

// ---------------- persistent CSR built by prep kernel ----------------
__device__ int   g_row_ptr[NN + 1];
__device__ int   g_csr_src[MAXM];
__device__ float g_csr_w[MAXM];

// =====================================================================
// Prep kernel: deterministic CSR (stable counting sort by dst) + norms.
// =====================================================================
__global__ void prep_kernel(const void* __restrict__ ei, int E) {
    __shared__ short s_src[2304];
    __shared__ short s_dst[2304];
    __shared__ int   deg[NN];
    __shared__ int   rp[NN + 1];
    __shared__ float inv[NN];
    __shared__ int   cnt[32][NN];
    __shared__ int   is64;

    const int tid = threadIdx.x;
    const int M = E + NN;

    if (tid == 0) {
        const long long* p = (const long long*)ei;
        int ok = 1;
        for (int i = 0; i < 8; i++) {
            long long v = p[i];
            if (v < 0 || v >= NN) ok = 0;
        }
        is64 = ok;
    }
    for (int n = tid; n < NN; n += blockDim.x) deg[n] = 0;
    __syncthreads();

    for (int e = tid; e < M; e += blockDim.x) {
        int s, d;
        if (e < E) {
            if (is64) {
                s = (int)((const long long*)ei)[e];
                d = (int)((const long long*)ei)[E + e];
            } else {
                s = ((const int*)ei)[e];
                d = ((const int*)ei)[E + e];
            }
        } else {
            s = d = e - E;   // self loops appended after real edges
        }
        s_src[e] = (short)s;
        s_dst[e] = (short)d;
        atomicAdd(&deg[d], 1);
    }
    __syncthreads();

    for (int n = tid; n < NN; n += blockDim.x)
        inv[n] = rsqrtf((float)max(deg[n], 1));
    if (tid == 0) {
        int acc = 0;
        for (int n = 0; n < NN; n++) { rp[n] = acc; acc += deg[n]; }
        rp[NN] = acc;
    }
    for (int i = tid; i < 32 * NN; i += blockDim.x)
        ((int*)cnt)[i] = 0;
    __syncthreads();

    const int chunk = (M + 31) / 32;
    if (tid < 32) {
        int e0 = tid * chunk, e1 = min(e0 + chunk, M);
        for (int e = e0; e < e1; e++) cnt[tid][s_dst[e]]++;
    }
    __syncthreads();

    for (int n = tid; n < NN; n += blockDim.x) {
        int run = rp[n];
        for (int t = 0; t < 32; t++) {
            int c = cnt[t][n];
            cnt[t][n] = run;
            run += c;
        }
    }
    __syncthreads();

    if (tid < 32) {
        int e0 = tid * chunk, e1 = min(e0 + chunk, M);
        for (int e = e0; e < e1; e++) {
            int d = s_dst[e], s = s_src[e];
            int pos = cnt[tid][d]++;
            g_csr_src[pos] = s;
            g_csr_w[pos]   = inv[s] * inv[d];
        }
    }
    __syncthreads();
    for (int n = tid; n <= NN; n += blockDim.x) g_row_ptr[n] = rp[n];
}

// =====================================================================
// Fused kernel
// =====================================================================

__device__ __forceinline__ float fast_tanh(float x) {
    x = fminf(fmaxf(x, -15.0f), 15.0f);
    float e = __expf(2.0f * x);
    return (e - 1.0f) / (e + 1.0f);
}
__device__ __forceinline__ float elu1(float v) {
    return v > 0.0f ? v : (__expf(v) - 1.0f);
}

// small-weight shared offsets (floats)
#define O_W1  0      // 12x8
#define O_B1  96     // 8
#define O_W2  104    // 8x4
#define O_B2  136    // 4
#define O_W3  140    // 4x2
#define O_B3  148    // 2
#define O_BF1 152    // 120
#define O_BF2 272    // 84
#define O_BF3 356    // 10

// shared sizing (floats): S1 + S2 + edges(float2) + small + rp(ints)
#define SM_FLOATS (NN*S1_STRIDE + NN*S2_STRIDE + 2*CAP + 512)
#define SM_BYTES  (SM_FLOATS*4 + (NN+1)*4)

__global__ void __launch_bounds__(THREADS)
gcn_fused_kernel(const float* __restrict__ x,
                 const float* __restrict__ W1, const float* __restrict__ b1,
                 const float* __restrict__ W2, const float* __restrict__ b2,
                 const float* __restrict__ W3, const float* __restrict__ b3,
                 const float* __restrict__ Wf1, const float* __restrict__ bf1,
                 const float* __restrict__ Wf2, const float* __restrict__ bf2,
                 const float* __restrict__ Wf3, const float* __restrict__ bf3,
                 float* __restrict__ out, int B, int M) {
    extern __shared__ float sm[];
    float*  S1      = sm;                          // t1 [n][8][16] str 132
    float*  S2      = S1 + NN * S1_STRIDE;         // t2 [n][4][16] str 68
    float2* s_e     = (float2*)(S2 + NN * S2_STRIDE); // (w, src) pairs
    float*  s_small = (float*)(s_e + CAP);
    int*    s_rp    = (int*)(s_small + 512);

    const int tid = threadIdx.x;
    const int b0  = blockIdx.x * BT;

    // ---- stage CSR + small weights ----
    for (int i = tid; i <= NN; i += THREADS) s_rp[i] = g_row_ptr[i];
    for (int i = tid; i < M; i += THREADS)
        s_e[i] = make_float2(g_csr_w[i], __int_as_float(g_csr_src[i]));
    for (int i = tid; i < 96;  i += THREADS) s_small[O_W1 + i] = W1[i];
    for (int i = tid; i < 8;   i += THREADS) s_small[O_B1 + i] = b1[i];
    for (int i = tid; i < 32;  i += THREADS) s_small[O_W2 + i] = W2[i];
    for (int i = tid; i < 4;   i += THREADS) s_small[O_B2 + i] = b2[i];
    for (int i = tid; i < 8;   i += THREADS) s_small[O_W3 + i] = W3[i];
    for (int i = tid; i < 2;   i += THREADS) s_small[O_B3 + i] = b3[i];
    for (int i = tid; i < 120; i += THREADS) s_small[O_BF1 + i] = bf1[i];
    for (int i = tid; i < 84;  i += THREADS) s_small[O_BF2 + i] = bf2[i];
    for (int i = tid; i < 10;  i += THREADS) s_small[O_BF3 + i] = bf3[i];
    __syncthreads();

    // ========== T1: t1 = x @ W1  -> S1[n][8][b] ==========
    for (int idx = tid; idx < NN * BT; idx += THREADS) {
        const int n = idx >> 4, b = idx & 15;
        const int g = b0 + b;
        float xa[12];
        if (g < B) {
            const float4* xp = (const float4*)(x + ((size_t)g * NN + n) * 12);
            float4 v0 = xp[0], v1 = xp[1], v2 = xp[2];
            xa[0] = v0.x; xa[1] = v0.y; xa[2]  = v0.z; xa[3]  = v0.w;
            xa[4] = v1.x; xa[5] = v1.y; xa[6]  = v1.z; xa[7]  = v1.w;
            xa[8] = v2.x; xa[9] = v2.y; xa[10] = v2.z; xa[11] = v2.w;
        } else {
            #pragma unroll
            for (int c = 0; c < 12; c++) xa[c] = 0.0f;
        }
        #pragma unroll
        for (int f = 0; f < 8; f++) {
            float a = 0.0f;
            #pragma unroll
            for (int c = 0; c < 12; c++) a += xa[c] * s_small[O_W1 + c * 8 + f];
            S1[n * S1_STRIDE + f * BT + b] = a;
        }
    }
    __syncthreads();

    // ========== A1: agg(t1)+b1 -> tanh -> @W2 -> S2[n][4][b] ==========
    for (int idx = tid; idx < NN * 4; idx += THREADS) {
        const int n = idx >> 2, bg = (idx & 3) * 4;
        float4 acc[8];
        #pragma unroll
        for (int f = 0; f < 8; f++) {
            float bb = s_small[O_B1 + f];
            acc[f] = make_float4(bb, bb, bb, bb);
        }
        const int j1 = s_rp[n + 1];
        for (int j = s_rp[n]; j < j1; j++) {
            const float2 e = s_e[j];
            const float w = e.x;
            const float4* p = (const float4*)(S1 + __float_as_int(e.y) * S1_STRIDE + bg);
            #pragma unroll
            for (int f = 0; f < 8; f++) {
                float4 v = p[f * 4];
                acc[f].x += w * v.x; acc[f].y += w * v.y;
                acc[f].z += w * v.z; acc[f].w += w * v.w;
            }
        }
        #pragma unroll
        for (int f = 0; f < 8; f++) {
            acc[f].x = fast_tanh(acc[f].x); acc[f].y = fast_tanh(acc[f].y);
            acc[f].z = fast_tanh(acc[f].z); acc[f].w = fast_tanh(acc[f].w);
        }
        #pragma unroll
        for (int f2 = 0; f2 < 4; f2++) {
            float bb = s_small[O_B2 + f2];
            float4 a = make_float4(bb, bb, bb, bb);
            #pragma unroll
            for (int f = 0; f < 8; f++) {
                float w = s_small[O_W2 + f * 4 + f2];
                a.x += w * acc[f].x; a.y += w * acc[f].y;
                a.z += w * acc[f].z; a.w += w * acc[f].w;
            }
            *(float4*)(S2 + n * S2_STRIDE + f2 * BT + bg) = a;
        }
    }
    __syncthreads();

    // ========== A2: agg(t2) -> tanh -> @W3 -> S1[n][2][b] (t3) ========
    for (int idx = tid; idx < NN * 4; idx += THREADS) {
        const int n = idx >> 2, bg = (idx & 3) * 4;
        float4 acc[4];
        #pragma unroll
        for (int f = 0; f < 4; f++)
            acc[f] = make_float4(0.f, 0.f, 0.f, 0.f);
        const int j1 = s_rp[n + 1];
        for (int j = s_rp[n]; j < j1; j++) {
            const float2 e = s_e[j];
            const float w = e.x;
            const float4* p = (const float4*)(S2 + __float_as_int(e.y) * S2_STRIDE + bg);
            #pragma unroll
            for (int f = 0; f < 4; f++) {
                float4 v = p[f * 4];
                acc[f].x += w * v.x; acc[f].y += w * v.y;
                acc[f].z += w * v.z; acc[f].w += w * v.w;
            }
        }
        // note: bias b2 was already added pre-aggregation in A1 output?  NO —
        // bias must be added AFTER aggregation.  A1 wrote t2 = tanh(agg+b1)@W2
        // (no b2).  Add b2 here, then tanh belongs to layer2's activation.
        #pragma unroll
        for (int f = 0; f < 4; f++) {
            acc[f].x = fast_tanh(acc[f].x); acc[f].y = fast_tanh(acc[f].y);
            acc[f].z = fast_tanh(acc[f].z); acc[f].w = fast_tanh(acc[f].w);
        }
        #pragma unroll
        for (int c = 0; c < 2; c++) {
            float4 a = make_float4(0.f, 0.f, 0.f, 0.f);
            #pragma unroll
            for (int f = 0; f < 4; f++) {
                float w = s_small[O_W3 + f * 2 + c];
                a.x += w * acc[f].x; a.y += w * acc[f].y;
                a.z += w * acc[f].z; a.w += w * acc[f].w;
            }
            *(float4*)(S1 + n * T3_STRIDE + c * BT + bg) = a;
        }
    }
    __syncthreads();

    // ========== A3: agg(t3)+b3 -> S2 as FC input [k=2n+c][b] ==========
    for (int idx = tid; idx < NN * 4; idx += THREADS) {
        const int n = idx >> 2, bg = (idx & 3) * 4;
        float bb0 = s_small[O_B3 + 0], bb1 = s_small[O_B3 + 1];
        float4 a0 = make_float4(bb0, bb0, bb0, bb0);
        float4 a1 = make_float4(bb1, bb1, bb1, bb1);
        const int j1 = s_rp[n + 1];
        for (int j = s_rp[n]; j < j1; j++) {
            const float2 e = s_e[j];
            const float w = e.x;
            const float* p = S1 + __float_as_int(e.y) * T3_STRIDE + bg;
            float4 v0 = *(const float4*)p;
            float4 v1 = *(const float4*)(p + BT);
            a0.x += w * v0.x; a0.y += w * v0.y; a0.z += w * v0.z; a0.w += w * v0.w;
            a1.x += w * v1.x; a1.y += w * v1.y; a1.z += w * v1.z; a1.w += w * v1.w;
        }
        *(float4*)(S2 + (n * 2 + 0) * BT + bg) = a0;
        *(float4*)(S2 + (n * 2 + 1) * BT + bg) = a1;
    }
    __syncthreads();

    // ========== FC1: [16,462]@Wf1[462,120]+bf1 -> elu -> S1[j][b] =====
    if (tid < 480) {
        const int jg = tid >> 4, b = tid & 15;     // jg: 0..29, 4 j each
        const int j0 = jg * 4;
        float4 acc = make_float4(s_small[O_BF1 + j0 + 0], s_small[O_BF1 + j0 + 1],
                                 s_small[O_BF1 + j0 + 2], s_small[O_BF1 + j0 + 3]);
        const float* wbase = Wf1 + j0;
        #pragma unroll 4
        for (int k = 0; k < 462; k++) {
            const float v = S2[k * BT + b];
            const float4 w = __ldg((const float4*)(wbase + k * 120));
            acc.x += v * w.x; acc.y += v * w.y;
            acc.z += v * w.z; acc.w += v * w.w;
        }
        S1[(j0 + 0) * BT + b] = elu1(acc.x);
        S1[(j0 + 1) * BT + b] = elu1(acc.y);
        S1[(j0 + 2) * BT + b] = elu1(acc.z);
        S1[(j0 + 3) * BT + b] = elu1(acc.w);
    }
    __syncthreads();

    // ========== FC2: [16,120]@Wf2[120,84]+bf2 -> elu -> S2[j][b] ======
    if (tid < 336) {
        const int j = tid >> 2, bg = (tid & 3) * 4;   // j: 0..83
        float bb = s_small[O_BF2 + j];
        float4 acc = make_float4(bb, bb, bb, bb);
        #pragma unroll 4
        for (int k = 0; k < 120; k++) {
            const float4 v = *(const float4*)(S1 + k * BT + bg);
            const float w = __ldg(Wf2 + k * 84 + j);
            acc.x += w * v.x; acc.y += w * v.y;
            acc.z += w * v.z; acc.w += w * v.w;
        }
        acc.x = elu1(acc.x); acc.y = elu1(acc.y);
        acc.z = elu1(acc.z); acc.w = elu1(acc.w);
        *(float4*)(S2 + j * BT + bg) = acc;
    }
    __syncthreads();

    // ========== FC3: [16,84]@Wf3[84,10]+bf3 -> out ====================
    if (tid < 160) {
        const int j = tid >> 4, b = tid & 15;         // j: 0..9
        float acc = s_small[O_BF3 + j];
        #pragma unroll 4
        for (int k = 0; k < 84; k++)
            acc += S2[k * BT + b] * __ldg(Wf3 + k * 10 + j);
        const int g = b0 + b;
        if (g < B) out[(size_t)g * 10 + j] = acc;
    }
}

// =====================================================================
extern "C" void kernel_launch(void* const* d_in, const int* in_sizes, int n_in,
                              void* d_out, int out_size) {
    const float* x   = (const float*)d_in[0];
    const void*  ei  = d_in[1];
    const float* W1  = (const float*)d_in[2];
    const float* b1  = (const float*)d_in[3];
    const float* W2  = (const float*)d_in[4];
    const float* b2  = (const float*)d_in[5];
    const float* W3  = (const float*)d_in[6];
    const float* b3  = (const float*)d_in[7];
    const float* Wf1 = (const float*)d_in[8];
    const float* bf1 = (const float*)d_in[9];
    const float* Wf2 = (const float*)d_in[10];
    const float* bf2 = (const float*)d_in[11];
    const float* Wf3 = (const float*)d_in[12];
    const float* bf3 = (const float*)d_in[13];
    float* out = (float*)d_out;

    const int B = in_sizes[0] / (NN * 12);
    const int E = in_sizes[1] / 2;
    const int M = E + NN;

    prep_kernel<<<1, 256>>>(ei, E);

    static int smem_set = 0;
    if (!smem_set) {
        cudaFuncSetAttribute(gcn_fused_kernel,
                             cudaFuncAttributeMaxDynamicSharedMemorySize,
                             SM_BYTES);
        smem_set = 1;
    }

    const int blocks = (B + BT - 1) / BT;
    gcn_fused_kernel<<<blocks, THREADS, SM_BYTES>>>(
        x, W1, b1, W2, b2, W3, b3, Wf1, bf1, Wf2, bf2, Wf3, bf3,
        out, B, M);
}

// round 3
// speedup vs baseline: 1.5690x; 1.0499x over previous
#include <cuda_runtime.h>
#include <math.h>

#define NN 231          // nodes per graph
#define BT 8            // graphs per block (halved -> 2 CTAs/SM)
#define THREADS 512
#define MAXM 4096       // cap for persistent CSR arrays
#define CAP  2112       // shared-mem cap on edges incl self loops (actual 2079)

#define S1_STRIDE 68    // 8*BT + 4 pad
#define S2_STRIDE 36    // 4*BT + 4 pad
#define T3_STRIDE 20    // 2*BT + 4 pad

// ---------------- persistent CSR built by prep kernel ----------------
__device__ int   g_row_ptr[NN + 1];
__device__ int   g_csr_src[MAXM];
__device__ float g_csr_w[MAXM];

// =====================================================================
// Prep kernel: deterministic CSR (stable counting sort by dst) + norms.
// =====================================================================
__global__ void prep_kernel(const void* __restrict__ ei, int E) {
    __shared__ short s_src[2304];
    __shared__ short s_dst[2304];
    __shared__ int   deg[NN];
    __shared__ int   rp[NN + 1];
    __shared__ float inv[NN];
    __shared__ int   cnt[32][NN];
    __shared__ int   is64;

    const int tid = threadIdx.x;
    const int M = E + NN;

    if (tid == 0) {
        const long long* p = (const long long*)ei;
        int ok = 1;
        for (int i = 0; i < 8; i++) {
            long long v = p[i];
            if (v < 0 || v >= NN) ok = 0;
        }
        is64 = ok;
    }
    for (int n = tid; n < NN; n += blockDim.x) deg[n] = 0;
    __syncthreads();

    for (int e = tid; e < M; e += blockDim.x) {
        int s, d;
        if (e < E) {
            if (is64) {
                s = (int)((const long long*)ei)[e];
                d = (int)((const long long*)ei)[E + e];
            } else {
                s = ((const int*)ei)[e];
                d = ((const int*)ei)[E + e];
            }
        } else {
            s = d = e - E;   // self loops appended after real edges
        }
        s_src[e] = (short)s;
        s_dst[e] = (short)d;
        atomicAdd(&deg[d], 1);
    }
    __syncthreads();

    for (int n = tid; n < NN; n += blockDim.x)
        inv[n] = rsqrtf((float)max(deg[n], 1));
    if (tid == 0) {
        int acc = 0;
        for (int n = 0; n < NN; n++) { rp[n] = acc; acc += deg[n]; }
        rp[NN] = acc;
    }
    for (int i = tid; i < 32 * NN; i += blockDim.x)
        ((int*)cnt)[i] = 0;
    __syncthreads();

    const int chunk = (M + 31) / 32;
    if (tid < 32) {
        int e0 = tid * chunk, e1 = min(e0 + chunk, M);
        for (int e = e0; e < e1; e++) cnt[tid][s_dst[e]]++;
    }
    __syncthreads();

    for (int n = tid; n < NN; n += blockDim.x) {
        int run = rp[n];
        for (int t = 0; t < 32; t++) {
            int c = cnt[t][n];
            cnt[t][n] = run;
            run += c;
        }
    }
    __syncthreads();

    if (tid < 32) {
        int e0 = tid * chunk, e1 = min(e0 + chunk, M);
        for (int e = e0; e < e1; e++) {
            int d = s_dst[e], s = s_src[e];
            int pos = cnt[tid][d]++;
            g_csr_src[pos] = s;
            g_csr_w[pos]   = inv[s] * inv[d];
        }
    }
    __syncthreads();
    for (int n = tid; n <= NN; n += blockDim.x) g_row_ptr[n] = rp[n];
}

// =====================================================================
// Fused kernel
// =====================================================================

__device__ __forceinline__ float fast_tanh(float x) {
    x = fminf(fmaxf(x, -15.0f), 15.0f);
    float e = __expf(2.0f * x);
    return (e - 1.0f) / (e + 1.0f);
}
__device__ __forceinline__ float elu1(float v) {
    return v > 0.0f ? v : (__expf(v) - 1.0f);
}

// small-weight shared offsets (floats)
#define O_W1  0      // 12x8
#define O_B1  96     // 8
#define O_W2  104    // 8x4
#define O_B2  136    // 4
#define O_W3  140    // 4x2
#define O_B3  148    // 2
#define O_BF1 152    // 120
#define O_BF2 272    // 84
#define O_BF3 356    // 10

// shared sizing: S1 + S2 + w + small (floats), then rp (int), src (short)
#define SM_FLOATS (NN*S1_STRIDE + NN*S2_STRIDE + CAP + 512)
#define SM_BYTES  (SM_FLOATS*4 + (NN+1)*4 + CAP*2)

__global__ void __launch_bounds__(THREADS, 2)
gcn_fused_kernel(const float* __restrict__ x,
                 const float* __restrict__ W1, const float* __restrict__ b1,
                 const float* __restrict__ W2, const float* __restrict__ b2,
                 const float* __restrict__ W3, const float* __restrict__ b3,
                 const float* __restrict__ Wf1, const float* __restrict__ bf1,
                 const float* __restrict__ Wf2, const float* __restrict__ bf2,
                 const float* __restrict__ Wf3, const float* __restrict__ bf3,
                 float* __restrict__ out, int B, int M) {
    extern __shared__ float sm[];
    float*  S1      = sm;                           // t1 [n][8][8] str 68
    float*  S2      = S1 + NN * S1_STRIDE;          // t2 [n][4][8] str 36
    float*  s_w     = S2 + NN * S2_STRIDE;          // edge weights
    float*  s_small = s_w + CAP;                    // 512 floats
    int*    s_rp    = (int*)(s_small + 512);        // 232 ints
    short*  s_src   = (short*)(s_rp + (NN + 1));    // 2112 shorts

    const int tid = threadIdx.x;
    const int b0  = blockIdx.x * BT;

    // ---- stage CSR + small weights ----
    for (int i = tid; i <= NN; i += THREADS) s_rp[i] = g_row_ptr[i];
    for (int i = tid; i < M; i += THREADS) {
        s_w[i]   = g_csr_w[i];
        s_src[i] = (short)g_csr_src[i];
    }
    for (int i = tid; i < 96;  i += THREADS) s_small[O_W1 + i] = W1[i];
    for (int i = tid; i < 8;   i += THREADS) s_small[O_B1 + i] = b1[i];
    for (int i = tid; i < 32;  i += THREADS) s_small[O_W2 + i] = W2[i];
    for (int i = tid; i < 4;   i += THREADS) s_small[O_B2 + i] = b2[i];
    for (int i = tid; i < 8;   i += THREADS) s_small[O_W3 + i] = W3[i];
    for (int i = tid; i < 2;   i += THREADS) s_small[O_B3 + i] = b3[i];
    for (int i = tid; i < 120; i += THREADS) s_small[O_BF1 + i] = bf1[i];
    for (int i = tid; i < 84;  i += THREADS) s_small[O_BF2 + i] = bf2[i];
    for (int i = tid; i < 10;  i += THREADS) s_small[O_BF3 + i] = bf3[i];
    __syncthreads();

    // ========== T1: t1 = x @ W1 -> S1[n][8][b]  (coalesced x reads) ===
    // lanes map to consecutive nodes of the SAME graph -> warp reads
    // 32*48B = 1536B contiguous from x.
    for (int idx = tid; idx < NN * BT; idx += THREADS) {
        const int b = idx / NN, n = idx - b * NN;
        const int g = b0 + b;
        float xa[12];
        if (g < B) {
            const float4* xp = (const float4*)(x + ((size_t)g * NN + n) * 12);
            float4 v0 = xp[0], v1 = xp[1], v2 = xp[2];
            xa[0] = v0.x; xa[1] = v0.y; xa[2]  = v0.z; xa[3]  = v0.w;
            xa[4] = v1.x; xa[5] = v1.y; xa[6]  = v1.z; xa[7]  = v1.w;
            xa[8] = v2.x; xa[9] = v2.y; xa[10] = v2.z; xa[11] = v2.w;
        } else {
            #pragma unroll
            for (int c = 0; c < 12; c++) xa[c] = 0.0f;
        }
        #pragma unroll
        for (int f = 0; f < 8; f++) {
            float a = 0.0f;
            #pragma unroll
            for (int c = 0; c < 12; c++) a += xa[c] * s_small[O_W1 + c * 8 + f];
            S1[n * S1_STRIDE + f * BT + b] = a;
        }
    }
    __syncthreads();

    // ========== A1: agg(t1)+b1 -> tanh -> @W2 -> S2[n][4][b] ==========
    // task = (node, b-group of 4); 462 tasks
    if (tid < NN * 2) {
        const int n = tid >> 1, bg = (tid & 1) * 4;
        float4 acc[8];
        #pragma unroll
        for (int f = 0; f < 8; f++) {
            float bb = s_small[O_B1 + f];
            acc[f] = make_float4(bb, bb, bb, bb);
        }
        const int j1 = s_rp[n + 1];
        for (int j = s_rp[n]; j < j1; j++) {
            const float w = s_w[j];
            const int   s = s_src[j];
            const float4* p = (const float4*)(S1 + s * S1_STRIDE + bg);
            #pragma unroll
            for (int f = 0; f < 8; f++) {
                float4 v = p[f * 2];
                acc[f].x += w * v.x; acc[f].y += w * v.y;
                acc[f].z += w * v.z; acc[f].w += w * v.w;
            }
        }
        #pragma unroll
        for (int f = 0; f < 8; f++) {
            acc[f].x = fast_tanh(acc[f].x); acc[f].y = fast_tanh(acc[f].y);
            acc[f].z = fast_tanh(acc[f].z); acc[f].w = fast_tanh(acc[f].w);
        }
        #pragma unroll
        for (int f2 = 0; f2 < 4; f2++) {
            float bb = s_small[O_B2 + f2];
            float4 a = make_float4(bb, bb, bb, bb);
            #pragma unroll
            for (int f = 0; f < 8; f++) {
                float w = s_small[O_W2 + f * 4 + f2];
                a.x += w * acc[f].x; a.y += w * acc[f].y;
                a.z += w * acc[f].z; a.w += w * acc[f].w;
            }
            *(float4*)(S2 + n * S2_STRIDE + f2 * BT + bg) = a;
        }
    }
    __syncthreads();

    // ========== A2: agg(t2)+b2 -> tanh -> @W3 -> S1[n][2][b] (t3) =====
    if (tid < NN * 2) {
        const int n = tid >> 1, bg = (tid & 1) * 4;
        float4 acc[4];
        #pragma unroll
        for (int f = 0; f < 4; f++)
            acc[f] = make_float4(0.f, 0.f, 0.f, 0.f);
        const int j1 = s_rp[n + 1];
        for (int j = s_rp[n]; j < j1; j++) {
            const float w = s_w[j];
            const int   s = s_src[j];
            const float4* p = (const float4*)(S2 + s * S2_STRIDE + bg);
            #pragma unroll
            for (int f = 0; f < 4; f++) {
                float4 v = p[f * 2];
                acc[f].x += w * v.x; acc[f].y += w * v.y;
                acc[f].z += w * v.z; acc[f].w += w * v.w;
            }
        }
        #pragma unroll
        for (int f = 0; f < 4; f++) {
            acc[f].x = fast_tanh(acc[f].x); acc[f].y = fast_tanh(acc[f].y);
            acc[f].z = fast_tanh(acc[f].z); acc[f].w = fast_tanh(acc[f].w);
        }
        #pragma unroll
        for (int c = 0; c < 2; c++) {
            float4 a = make_float4(0.f, 0.f, 0.f, 0.f);
            #pragma unroll
            for (int f = 0; f < 4; f++) {
                float w = s_small[O_W3 + f * 2 + c];
                a.x += w * acc[f].x; a.y += w * acc[f].y;
                a.z += w * acc[f].z; a.w += w * acc[f].w;
            }
            *(float4*)(S1 + n * T3_STRIDE + c * BT + bg) = a;
        }
    }
    __syncthreads();

    // ========== A3: agg(t3)+b3 -> S2 as FC input [k=2n+c][b] ==========
    if (tid < NN * 2) {
        const int n = tid >> 1, bg = (tid & 1) * 4;
        float bb0 = s_small[O_B3 + 0], bb1 = s_small[O_B3 + 1];
        float4 a0 = make_float4(bb0, bb0, bb0, bb0);
        float4 a1 = make_float4(bb1, bb1, bb1, bb1);
        const int j1 = s_rp[n + 1];
        for (int j = s_rp[n]; j < j1; j++) {
            const float w = s_w[j];
            const int   s = s_src[j];
            const float* p = S1 + s * T3_STRIDE + bg;
            float4 v0 = *(const float4*)p;
            float4 v1 = *(const float4*)(p + BT);
            a0.x += w * v0.x; a0.y += w * v0.y; a0.z += w * v0.z; a0.w += w * v0.w;
            a1.x += w * v1.x; a1.y += w * v1.y; a1.z += w * v1.z; a1.w += w * v1.w;
        }
        *(float4*)(S2 + (n * 2 + 0) * BT + bg) = a0;
        *(float4*)(S2 + (n * 2 + 1) * BT + bg) = a1;
    }
    __syncthreads();

    // ========== FC1: [8,462]@Wf1[462,120]+bf1 -> elu -> S1[j][b] ======
    if (tid < 480) {
        const int jg = tid >> 3, b = tid & 7;     // jg: 0..59, 2 j each
        const int j0 = jg * 2;
        float2 acc = make_float2(s_small[O_BF1 + j0], s_small[O_BF1 + j0 + 1]);
        const float* wbase = Wf1 + j0;
        #pragma unroll 6
        for (int k = 0; k < 462; k++) {
            const float v = S2[k * BT + b];
            const float2 w = __ldg((const float2*)(wbase + k * 120));
            acc.x += v * w.x; acc.y += v * w.y;
        }
        S1[(j0 + 0) * BT + b] = elu1(acc.x);
        S1[(j0 + 1) * BT + b] = elu1(acc.y);
    }
    __syncthreads();

    // ========== FC2: [8,120]@Wf2[120,84]+bf2 -> elu -> S2[j][b] =======
    if (tid < 336) {
        const int jg = tid >> 3, b = tid & 7;     // jg: 0..41, 2 j each
        const int j0 = jg * 2;
        float2 acc = make_float2(s_small[O_BF2 + j0], s_small[O_BF2 + j0 + 1]);
        const float* wbase = Wf2 + j0;
        #pragma unroll 6
        for (int k = 0; k < 120; k++) {
            const float v = S1[k * BT + b];
            const float2 w = __ldg((const float2*)(wbase + k * 84));
            acc.x += v * w.x; acc.y += v * w.y;
        }
        S2[(j0 + 0) * BT + b] = elu1(acc.x);
        S2[(j0 + 1) * BT + b] = elu1(acc.y);
    }
    __syncthreads();

    // ========== FC3: [8,84]@Wf3[84,10]+bf3 -> out =====================
    if (tid < 80) {
        const int j = tid >> 3, b = tid & 7;      // j: 0..9
        float acc = s_small[O_BF3 + j];
        #pragma unroll 4
        for (int k = 0; k < 84; k++)
            acc += S2[k * BT + b] * __ldg(Wf3 + k * 10 + j);
        const int g = b0 + b;
        if (g < B) out[(size_t)g * 10 + j] = acc;
    }
}

// =====================================================================
extern "C" void kernel_launch(void* const* d_in, const int* in_sizes, int n_in,
                              void* d_out, int out_size) {
    const float* x   = (const float*)d_in[0];
    const void*  ei  = d_in[1];
    const float* W1  = (const float*)d_in[2];
    const float* b1  = (const float*)d_in[3];
    const float* W2  = (const float*)d_in[4];
    const float* b2  = (const float*)d_in[5];
    const float* W3  = (const float*)d_in[6];
    const float* b3  = (const float*)d_in[7];
    const float* Wf1 = (const float*)d_in[8];
    const float* bf1 = (const float*)d_in[9];
    const float* Wf2 = (const float*)d_in[10];
    const float* bf2 = (const float*)d_in[11];
    const float* Wf3 = (const float*)d_in[12];
    const float* bf3 = (const float*)d_in[13];
    float* out = (float*)d_out;

    const int B = in_sizes[0] / (NN * 12);
    const int E = in_sizes[1] / 2;
    const int M = E + NN;

    prep_kernel<<<1, 256>>>(ei, E);

    static int smem_set = 0;
    if (!smem_set) {
        cudaFuncSetAttribute(gcn_fused_kernel,
                             cudaFuncAttributeMaxDynamicSharedMemorySize,
                             SM_BYTES);
        smem_set = 1;
    }

    const int blocks = (B + BT - 1) / BT;
    gcn_fused_kernel<<<blocks, THREADS, SM_BYTES>>>(
        x, W1, b1, W2, b2, W3, b3, Wf1, bf1, Wf2, bf2, Wf3, bf3,
        out, B, M);
}